// round 1
// baseline (speedup 1.0000x reference)
#include <cuda_runtime.h>
#include <cuda_bf16.h>
#include <cstdint>

// Problem constants (fixed shapes)
#define BB   2
#define NQ   256
#define ED   512
#define HH   150
#define HP   152          // H padded to multiple of 4 for f32x2/LDS.128
#define EC   64           // e-chunk for stage-1 tiling
#define GJP  257          // gjs pitch (odd -> conflict-free)

// smem layout (in floats)
#define S_PERSIST (2*HP)                    // his + b1s
#define S_GI      (ED)
#define S_SW      (EC*HP)
#define S_GJS     (EC*GJP)
#define S_HSM     (NQ*HP/2)                 // bf16 hidden tile occupies this many float slots
#define S_W2      (HP*HP)
#define S_STAGE2  (S_HSM + S_W2 + 2*HP)
#define SMEM_FLOATS (S_PERSIST + S_STAGE2)  // stage2 union is the larger one (42864+304)
#define SMEM_BYTES  (SMEM_FLOATS * 4)

// Precomputed hi / hj
__device__ float d_hi[BB*NQ*HH];
__device__ float d_hj[BB*NQ*HH];

#define FMA2(accv, wv, av) \
    asm("fma.rn.f32x2 %0, %1, %2, %0;" : "+l"(accv) : "l"(wv), "l"(av))

__device__ __forceinline__ unsigned long long pack2(float a) {
    unsigned long long r;
    asm("mov.b64 %0, {%1, %1};" : "=l"(r) : "f"(a));
    return r;
}
__device__ __forceinline__ void unpack2(unsigned long long v, float& lo, float& hi) {
    asm("mov.b64 {%0, %1}, %2;" : "=f"(lo), "=f"(hi) : "l"(v));
}

// ---------------------------------------------------------------------------
// Kernel A: hi[b,n,h] = sum_e g[b,n,e] * W1a[e,h];  hj with W1b.
// ---------------------------------------------------------------------------
__global__ void pre_hihj_kernel(const float* __restrict__ g,
                                const float* __restrict__ W1) {
    int n = blockIdx.x, b = blockIdx.y;
    __shared__ float gs[ED];
    const float* grow = g + ((size_t)(b*NQ + n))*ED;
    for (int e = threadIdx.x; e < ED; e += blockDim.x) gs[e] = grow[e];
    __syncthreads();
    int h = threadIdx.x;
    if (h < HH) {
        float s1 = 0.f, s2 = 0.f;
        #pragma unroll 4
        for (int e = 0; e < ED; e++) {
            float ge = gs[e];
            s1 = fmaf(ge, W1[e*HH + h], s1);            // W1a
            s2 = fmaf(ge, W1[(ED + e)*HH + h], s2);     // W1b
        }
        d_hi[(b*NQ + n)*HH + h] = s1;
        d_hj[(b*NQ + n)*HH + h] = s2;
    }
}

// ---------------------------------------------------------------------------
// Kernel B: one CTA per (b, i). thread t = j.
//  stage1: acc[h] = hij[b,i,j,h] = sum_e (g_i[e]*W1c[e,h]) * g_j[e]
//  stage2: h = relu(acc + hi_i + hj_j + b1); h2 = relu(h@W2 + b2);
//          pair = h2@W3 + b3; out = (m_i + m_j + pair)/3
// ---------------------------------------------------------------------------
__global__ __launch_bounds__(NQ, 1)
void pair_main_kernel(const float* __restrict__ g,
                      const float* __restrict__ m,
                      const float* __restrict__ W1,
                      const float* __restrict__ b1,
                      const float* __restrict__ W2,
                      const float* __restrict__ b2,
                      const float* __restrict__ W3,
                      const float* __restrict__ b3,
                      float* __restrict__ out) {
    const int i = blockIdx.x, b = blockIdx.y, t = threadIdx.x;

    extern __shared__ float smem[];
    float* his = smem;                 // [HP] persist
    float* b1s = smem + HP;            // [HP] persist
    float* dyn = smem + S_PERSIST;     // union region
    // stage1 views
    float* gi  = dyn;                  // [ED]
    float* sw  = dyn + S_GI;           // [EC][HP]   (scaled W1c chunk)
    float* gjs = dyn + S_GI + S_SW;    // [EC][GJP]
    // stage2 views
    __nv_bfloat16* hsm = (__nv_bfloat16*)dyn;   // [NQ][HP] bf16
    float* W2s = dyn + S_HSM;          // [HP][HP], zero padded
    float* b2s = W2s + S_W2;           // [HP]
    float* W3s = b2s + HP;             // [HP]

    // persistent loads
    for (int h = t; h < HP; h += NQ) {
        his[h] = (h < HH) ? d_hi[(b*NQ + i)*HH + h] : 0.f;
        b1s[h] = (h < HH) ? b1[h] : 0.f;
    }
    for (int e = t; e < ED; e += NQ) gi[e] = g[((size_t)(b*NQ + i))*ED + e];

    unsigned long long acc[HP/2];
    #pragma unroll
    for (int k = 0; k < HP/2; k++) acc[k] = 0ull;

    const float* W1c = W1 + 2*ED*HH;

    // -------- stage 1: hij --------
    for (int e0 = 0; e0 < ED; e0 += EC) {
        __syncthreads();   // prev compute done (and initial loads visible)
        // scaled W1c chunk: sw[e][h] = g_i[e0+e] * W1c[e0+e, h]
        for (int idx = t; idx < EC*HP; idx += NQ) {
            int e = idx / HP, h = idx - e*HP;
            sw[idx] = (h < HH) ? W1c[(e0 + e)*HH + h] * gi[e0 + e] : 0.f;
        }
        // gjs[e][j] = g[b, j, e0+e]  (coalesced gmem, conflict-free smem)
        for (int idx = t; idx < EC*NQ; idx += NQ) {
            int jj = idx >> 6, e = idx & 63;
            gjs[e*GJP + jj] = g[((size_t)(b*NQ + jj))*ED + e0 + e];
        }
        __syncthreads();

        #pragma unroll 2
        for (int e = 0; e < EC; e++) {
            unsigned long long a2 = pack2(gjs[e*GJP + t]);
            const ulonglong2* wp = (const ulonglong2*)(sw + e*HP);
            #pragma unroll
            for (int k2 = 0; k2 < HP/4; k2++) {
                ulonglong2 w = wp[k2];
                FMA2(acc[2*k2 + 0], w.x, a2);
                FMA2(acc[2*k2 + 1], w.y, a2);
            }
        }
    }
    __syncthreads();  // done reading sw/gjs; union region about to be reused

    // -------- transition: relu(hij + hi + hj + b1) -> bf16 row --------
    const float* hjrow = d_hj + (b*NQ + t)*HH;
    __nv_bfloat16* hrow = hsm + t*HP;
    #pragma unroll
    for (int k = 0; k < HP/2; k++) {
        float v0, v1;
        unpack2(acc[k], v0, v1);
        int h0 = 2*k, h1 = 2*k + 1;
        v0 += his[h0] + b1s[h0] + ((h0 < HH) ? hjrow[h0] : 0.f);
        v1 += his[h1] + b1s[h1] + ((h1 < HH) ? hjrow[h1] : 0.f);
        v0 = fmaxf(v0, 0.f);
        v1 = fmaxf(v1, 0.f);
        ((__nv_bfloat162*)hrow)[k] = __floats2bfloat162_rn(v0, v1);
    }

    // load W2 (zero padded), b2, W3
    for (int idx = t; idx < HP*HP; idx += NQ) {
        int hh = idx / HP, k = idx - hh*HP;
        W2s[idx] = (hh < HH && k < HH) ? W2[hh*HH + k] : 0.f;
    }
    for (int idx = t; idx < HP; idx += NQ) {
        b2s[idx] = (idx < HH) ? b2[idx] : 0.f;
        W3s[idx] = (idx < HH) ? W3[idx] : 0.f;
    }
    __syncthreads();

    // -------- stage 2: h2 = relu(h @ W2 + b2) --------
    #pragma unroll
    for (int k = 0; k < HP/2; k++) acc[k] = 0ull;

    #pragma unroll 2
    for (int hh = 0; hh < HH; hh++) {
        float a = __bfloat162float(hrow[hh]);
        unsigned long long a2 = pack2(a);
        const ulonglong2* wp = (const ulonglong2*)(W2s + hh*HP);
        #pragma unroll
        for (int k2 = 0; k2 < HP/4; k2++) {
            ulonglong2 w = wp[k2];
            FMA2(acc[2*k2 + 0], w.x, a2);
            FMA2(acc[2*k2 + 1], w.y, a2);
        }
    }

    // -------- stage 3: pair = relu(h2) @ W3 + b3; combine --------
    float pair = b3[0];
    #pragma unroll
    for (int k = 0; k < HP/2; k++) {
        float v0, v1;
        unpack2(acc[k], v0, v1);
        v0 = fmaxf(v0 + b2s[2*k],     0.f);
        v1 = fmaxf(v1 + b2s[2*k + 1], 0.f);
        pair = fmaf(v0, W3s[2*k], pair);
        pair = fmaf(v1, W3s[2*k + 1], pair);
    }

    float res = (m[b*NQ + i] + m[b*NQ + t] + pair) * (1.0f/3.0f);
    out[((size_t)(b*NQ + i))*NQ + t] = res;
}

// ---------------------------------------------------------------------------
extern "C" void kernel_launch(void* const* d_in, const int* in_sizes, int n_in,
                              void* d_out, int out_size) {
    const float* g  = (const float*)d_in[0];   // [B,N,E]
    const float* m  = (const float*)d_in[1];   // [B,N,1]
    const float* W1 = (const float*)d_in[2];   // [3E,H]
    const float* b1 = (const float*)d_in[3];   // [H]
    const float* W2 = (const float*)d_in[4];   // [H,H]
    const float* b2 = (const float*)d_in[5];   // [H]
    const float* W3 = (const float*)d_in[6];   // [H,1]
    const float* b3 = (const float*)d_in[7];   // [1]
    float* out = (float*)d_out;                // [B,N,N,1]

    cudaFuncSetAttribute(pair_main_kernel,
                         cudaFuncAttributeMaxDynamicSharedMemorySize, SMEM_BYTES);

    pre_hihj_kernel<<<dim3(NQ, BB), 160>>>(g, W1);
    pair_main_kernel<<<dim3(NQ, BB), NQ, SMEM_BYTES>>>(g, m, W1, b1, W2, b2, W3, b3, out);
}

// round 3
// speedup vs baseline: 7.2041x; 7.2041x over previous
#include <cuda_runtime.h>
#include <cuda_bf16.h>
#include <cstdint>

#define BB 2
#define NQ 256
#define ED 512
#define HH 150
#define HP 152
#define KC 128            // stage-1 k-chunk
#define K2P 160           // stage-2 K padded
#define NT 19             // n-tiles of 8 -> 152

#define P1 272            // stage-1 smem row pitch bytes (17 * 16B, odd units)
#define P2 336            // stage-2 smem row pitch bytes (21 * 16B, odd units)

// ---------------- device scratch ----------------
__device__ __nv_bfloat16 d_gbf[BB*NQ*ED];     // g in bf16
__device__ float         d_w1ct[HP*ED];       // W1c^T fp32 [h][e]
__device__ __nv_bfloat16 d_w2t[HP*K2P];       // W2^T bf16 [n][k] zero-padded
__device__ float         d_hi[BB*NQ*HP];      // hi + b1
__device__ float         d_hj[BB*NQ*HP];      // hj

// ---------------- smem layout (bytes) ----------------
#define SM_GI   0                       // 512 f
#define SM_HI   2048                    // 152 f
#define SM_B2S  2656
#define SM_W3S  3264
#define SM_U    3968                    // union base (16B aligned)
#define OFF_A1  0                       // 256*272 = 69632
#define OFF_B1  69632                   // 152*272 = 41344   (end 110976)
#define OFF_H   0                       // 256*336 = 86016
#define OFF_W2  86016                   // 152*336 = 51072   (end 137088)
#define SMEM_BYTES (SM_U + 137088)      // 141056

__device__ __forceinline__ uint32_t smem_u32(const void* p) {
    uint32_t a;
    asm("{ .reg .u64 t; cvta.to.shared.u64 t, %1; cvt.u32.u64 %0, t; }" : "=r"(a) : "l"(p));
    return a;
}
__device__ __forceinline__ void ldsm_x4(uint32_t& r0, uint32_t& r1, uint32_t& r2, uint32_t& r3,
                                        uint32_t addr) {
    asm volatile("ldmatrix.sync.aligned.m8n8.x4.shared.b16 {%0,%1,%2,%3}, [%4];"
                 : "=r"(r0), "=r"(r1), "=r"(r2), "=r"(r3) : "r"(addr));
}
__device__ __forceinline__ void ldsm_x2(uint32_t& r0, uint32_t& r1, uint32_t addr) {
    asm volatile("ldmatrix.sync.aligned.m8n8.x2.shared.b16 {%0,%1}, [%2];"
                 : "=r"(r0), "=r"(r1) : "r"(addr));
}
__device__ __forceinline__ void mma16816(float* d, uint32_t a0, uint32_t a1, uint32_t a2,
                                         uint32_t a3, uint32_t b0, uint32_t b1) {
    asm volatile("mma.sync.aligned.m16n8k16.row.col.f32.bf16.bf16.f32 "
                 "{%0,%1,%2,%3}, {%4,%5,%6,%7}, {%8,%9}, {%0,%1,%2,%3};"
                 : "+f"(d[0]), "+f"(d[1]), "+f"(d[2]), "+f"(d[3])
                 : "r"(a0), "r"(a1), "r"(a2), "r"(a3), "r"(b0), "r"(b1));
}

// ---------------- prekernels ----------------
__global__ void prep_gbf(const float* __restrict__ g) {
    int idx = blockIdx.x * blockDim.x + threadIdx.x;
    if (idx < BB*NQ*ED) d_gbf[idx] = __float2bfloat16(g[idx]);
}
__global__ void prep_w1ct(const float* __restrict__ W1) {
    int h = blockIdx.x, e = threadIdx.x;   // 152 x 512
    d_w1ct[h*ED + e] = (h < HH) ? W1[(2*ED + e)*HH + h] : 0.f;
}
__global__ void prep_w2t(const float* __restrict__ W2) {
    int o = blockIdx.x, k = threadIdx.x;   // 152 x 160
    float v = (o < HH && k < HH) ? W2[k*HH + o] : 0.f;
    d_w2t[o*K2P + k] = __float2bfloat16(v);
}
__global__ void prep_hihj(const float* __restrict__ g, const float* __restrict__ W1,
                          const float* __restrict__ b1) {
    int n = blockIdx.x, b = blockIdx.y;
    __shared__ float gs[ED];
    const float* grow = g + (size_t)(b*NQ + n)*ED;
    for (int e = threadIdx.x; e < ED; e += blockDim.x) gs[e] = grow[e];
    __syncthreads();
    int h = threadIdx.x;
    if (h < HP) {
        float s1 = 0.f, s2 = 0.f;
        if (h < HH) {
            #pragma unroll 4
            for (int e = 0; e < ED; e++) {
                s1 = fmaf(gs[e], W1[e*HH + h], s1);
                s2 = fmaf(gs[e], W1[(ED + e)*HH + h], s2);
            }
            s1 += b1[h];
        }
        d_hi[(b*NQ + n)*HP + h] = s1;
        d_hj[(b*NQ + n)*HP + h] = s2;
    }
}

// ---------------- main kernel: one CTA per (b,i) ----------------
__global__ __launch_bounds__(256, 1)
void pair_hmma_kernel(const float* __restrict__ g,
                      const float* __restrict__ m,
                      const float* __restrict__ b2,
                      const float* __restrict__ W3,
                      const float* __restrict__ b3,
                      float* __restrict__ out) {
    extern __shared__ char smc[];
    const int t = threadIdx.x, w = t >> 5, lane = t & 31;
    const int i = blockIdx.x, b = blockIdx.y;

    float* gi_s = (float*)(smc + SM_GI);
    float* hi_s = (float*)(smc + SM_HI);
    float* b2s  = (float*)(smc + SM_B2S);
    float* w3s  = (float*)(smc + SM_W3S);
    char*  A1   = smc + SM_U + OFF_A1;
    char*  B1   = smc + SM_U + OFF_B1;
    char*  Ht   = smc + SM_U + OFF_H;
    char*  W2s  = smc + SM_U + OFF_W2;

    for (int idx = t; idx < ED; idx += 256) gi_s[idx] = g[(size_t)(b*NQ + i)*ED + idx];
    for (int idx = t; idx < HP; idx += 256) {
        hi_s[idx] = d_hi[(b*NQ + i)*HP + idx];
        b2s[idx]  = (idx < HH) ? b2[idx] : 0.f;
        w3s[idx]  = (idx < HH) ? W3[idx] : 0.f;
    }
    __syncthreads();

    float acc[2][NT][4];
    #pragma unroll
    for (int a = 0; a < 2; a++)
        #pragma unroll
        for (int n = 0; n < NT; n++)
            #pragma unroll
            for (int k = 0; k < 4; k++) acc[a][n][k] = 0.f;

    const uint32_t A1a = smem_u32(A1), B1a = smem_u32(B1);
    const uint32_t Hta = smem_u32(Ht), W2a = smem_u32(W2s);

    // per-lane ldmatrix addressing
    const uint32_t a_row  = w*32 + (lane & 15);
    const uint32_t a_koff = (lane >> 4) * 16;              // bytes
    const uint32_t b_n    = lane & 7;
    const uint32_t b_koff = ((lane >> 3) & 1) * 16;

    // ================= stage 1 =================
    for (int c = 0; c < 4; c++) {
        if (c) __syncthreads();
        // A chunk: 256 rows x 128 bf16
        for (int idx = t; idx < 4096; idx += 256) {
            int row = idx >> 4, c16 = idx & 15;
            uint4 v = *(const uint4*)(d_gbf + (size_t)(b*NQ + row)*ED + c*KC + c16*8);
            *(uint4*)(A1 + row*P1 + c16*16) = v;
        }
        // B chunk: B1[h][e] = gi[e]*W1c[e][h], 152 rows x 128 bf16
        for (int idx = t; idx < HP*16; idx += 256) {
            int h = idx >> 4, c16 = idx & 15;
            const float* wr = d_w1ct + h*ED + c*KC + c16*8;
            const float* gp = gi_s + c*KC + c16*8;
            float4 wa = *(const float4*)wr, wb = *(const float4*)(wr + 4);
            float4 ga = *(const float4*)gp, gb = *(const float4*)(gp + 4);
            __nv_bfloat162 p0 = __floats2bfloat162_rn(wa.x*ga.x, wa.y*ga.y);
            __nv_bfloat162 p1 = __floats2bfloat162_rn(wa.z*ga.z, wa.w*ga.w);
            __nv_bfloat162 p2 = __floats2bfloat162_rn(wb.x*gb.x, wb.y*gb.y);
            __nv_bfloat162 p3 = __floats2bfloat162_rn(wb.z*gb.z, wb.w*gb.w);
            uint4 v = { *(uint32_t*)&p0, *(uint32_t*)&p1, *(uint32_t*)&p2, *(uint32_t*)&p3 };
            *(uint4*)(B1 + h*P1 + c16*16) = v;
        }
        __syncthreads();

        for (int ks = 0; ks < 8; ks++) {
            uint32_t a00, a01, a02, a03, a10, a11, a12, a13;
            uint32_t abase = A1a + a_row*P1 + a_koff + ks*32;
            ldsm_x4(a00, a01, a02, a03, abase);
            ldsm_x4(a10, a11, a12, a13, abase + 16*P1);
            uint32_t bbase = B1a + b_n*P1 + b_koff + ks*32;
            #pragma unroll
            for (int ni = 0; ni < NT; ni++) {
                uint32_t b0, b1r;
                ldsm_x2(b0, b1r, bbase + ni*(8*P1));
                mma16816(acc[0][ni], a00, a01, a02, a03, b0, b1r);
                mma16816(acc[1][ni], a10, a11, a12, a13, b0, b1r);
            }
        }
    }
    __syncthreads();   // stage-1 smem reads done; union region reused below

    // ================= epilogue 1: h = relu(D1 + hi + hj) -> bf16 smem =================
    // W2 copy into union
    for (int idx = t; idx < HP*20; idx += 256) {
        int o = idx / 20, c8 = idx % 20;
        uint4 v = *(const uint4*)(d_w2t + o*K2P + c8*8);
        *(uint4*)(W2s + o*P2 + c8*16) = v;
    }
    #pragma unroll
    for (int mi = 0; mi < 2; mi++) {
        #pragma unroll
        for (int rh = 0; rh < 2; rh++) {
            int row = w*32 + mi*16 + (lane >> 2) + rh*8;
            const float* hjr = d_hj + (size_t)(b*NQ + row)*HP;
            char* hrow = Ht + row*P2;
            #pragma unroll
            for (int ni = 0; ni < NT; ni++) {
                int col = ni*8 + (lane & 3)*2;
                float2 hj2 = *(const float2*)(hjr + col);
                float v0 = acc[mi][ni][rh*2 + 0] + hi_s[col]     + hj2.x;
                float v1 = acc[mi][ni][rh*2 + 1] + hi_s[col + 1] + hj2.y;
                __nv_bfloat162 p = __floats2bfloat162_rn(fmaxf(v0, 0.f), fmaxf(v1, 0.f));
                *(uint32_t*)(hrow + col*2) = *(uint32_t*)&p;
            }
            if ((lane & 3) == 0) {          // zero k-pad cols 152..159
                uint4 z = {0, 0, 0, 0};
                *(uint4*)(hrow + 304) = z;
            }
        }
    }
    __syncthreads();

    // ================= stage 2: D2 = h @ W2 (K = 160) =================
    #pragma unroll
    for (int a = 0; a < 2; a++)
        #pragma unroll
        for (int n = 0; n < NT; n++)
            #pragma unroll
            for (int k = 0; k < 4; k++) acc[a][n][k] = 0.f;

    for (int ks = 0; ks < 10; ks++) {
        uint32_t a00, a01, a02, a03, a10, a11, a12, a13;
        uint32_t abase = Hta + a_row*P2 + a_koff + ks*32;
        ldsm_x4(a00, a01, a02, a03, abase);
        ldsm_x4(a10, a11, a12, a13, abase + 16*P2);
        uint32_t bbase = W2a + b_n*P2 + b_koff + ks*32;
        #pragma unroll
        for (int ni = 0; ni < NT; ni++) {
            uint32_t b0, b1r;
            ldsm_x2(b0, b1r, bbase + ni*(8*P2));
            mma16816(acc[0][ni], a00, a01, a02, a03, b0, b1r);
            mma16816(acc[1][ni], a10, a11, a12, a13, b0, b1r);
        }
    }

    // ================= epilogue 2: pair = relu(D2 + b2) @ W3 + b3 =================
    const float mi_score = m[b*NQ + i];
    const float b3v = b3[0];
    float srow[2][2];
    #pragma unroll
    for (int mi = 0; mi < 2; mi++) {
        #pragma unroll
        for (int rh = 0; rh < 2; rh++) {
            float s = 0.f;
            #pragma unroll
            for (int ni = 0; ni < NT; ni++) {
                int col = ni*8 + (lane & 3)*2;
                float v0 = fmaxf(acc[mi][ni][rh*2 + 0] + b2s[col],     0.f);
                float v1 = fmaxf(acc[mi][ni][rh*2 + 1] + b2s[col + 1], 0.f);
                s = fmaf(v0, w3s[col], s);
                s = fmaf(v1, w3s[col + 1], s);
            }
            s += __shfl_xor_sync(0xFFFFFFFF, s, 1);
            s += __shfl_xor_sync(0xFFFFFFFF, s, 2);
            srow[mi][rh] = s;
        }
    }
    if ((lane & 3) == 0) {
        #pragma unroll
        for (int mi = 0; mi < 2; mi++) {
            #pragma unroll
            for (int rh = 0; rh < 2; rh++) {
                int row = w*32 + mi*16 + (lane >> 2) + rh*8;
                float pair = srow[mi][rh] + b3v;
                out[(size_t)(b*NQ + i)*NQ + row] =
                    (mi_score + m[b*NQ + row] + pair) * (1.0f/3.0f);
            }
        }
    }
}

// ---------------------------------------------------------------------------
extern "C" void kernel_launch(void* const* d_in, const int* in_sizes, int n_in,
                              void* d_out, int out_size) {
    const float* g  = (const float*)d_in[0];
    const float* m  = (const float*)d_in[1];
    const float* W1 = (const float*)d_in[2];
    const float* b1 = (const float*)d_in[3];
    const float* W2 = (const float*)d_in[4];
    const float* b2 = (const float*)d_in[5];
    const float* W3 = (const float*)d_in[6];
    const float* b3 = (const float*)d_in[7];
    float* out = (float*)d_out;

    cudaFuncSetAttribute(pair_hmma_kernel,
                         cudaFuncAttributeMaxDynamicSharedMemorySize, SMEM_BYTES);

    prep_gbf<<<(BB*NQ*ED + 255)/256, 256>>>(g);
    prep_w1ct<<<HP, ED>>>(W1);
    prep_w2t<<<HP, K2P>>>(W2);
    prep_hihj<<<dim3(NQ, BB), 160>>>(g, W1, b1);
    pair_hmma_kernel<<<dim3(NQ, BB), 256, SMEM_BYTES>>>(g, m, b2, W3, b3, out);
}